// round 16
// baseline (speedup 1.0000x reference)
#include <cuda_runtime.h>
#include <cuda_bf16.h>
#include <stdint.h>

#define OUT_CH 32
#define GRID   1184            // 148 SMs x 8 CTAs; fully resident single wave
#define TPB    256

__device__ float    g_Wt[100000 * OUT_CH];   // transposed W, L2-resident 12.8 MB
__device__ int      g_part2[GRID];           // per-CTA row-min partials (rewritten every call)
__device__ unsigned g_arrive;                // persistent barrier counter (monotonic, replay-safe)

// ---------------------------------------------------------------------------
// Single persistent kernel.
// Phase A: transpose W[32,N]->Wt[N,32], out[n,:]=b, per-CTA row-min partial.
// Barrier: single-wave ticket barrier (all GRID CTAs resident by construction:
//          __launch_bounds__(256,8) caps regs so 8 CTAs/SM is guaranteed).
// Phase B: scatter — 8 threads/edge-pair slot, 2 independent edges/thread,
//          grid-stride; red.global.add.v4.f32 to out.
// ---------------------------------------------------------------------------
__global__ void __launch_bounds__(TPB, 8) fused_kernel(
    const int* __restrict__ ei, const float* __restrict__ W,
    const float* __restrict__ b, float* __restrict__ out, int E, int N) {

    const int tid = threadIdx.x;
    const int gstride = GRID * TPB;

    // ---- Phase A1: transpose + out=b (grid-stride over nodes; 4-reg staging) ----
    for (int n = blockIdx.x * TPB + tid; n < N; n += gstride) {
        float4* wt = reinterpret_cast<float4*>(&g_Wt[(size_t)n * OUT_CH]);
        float4* o  = reinterpret_cast<float4*>(&out[(size_t)n * OUT_CH]);
        #pragma unroll
        for (int j = 0; j < 8; j++) {
            float4 q;
            q.x = __ldg(&W[(size_t)(4*j + 0) * N + n]);
            q.y = __ldg(&W[(size_t)(4*j + 1) * N + n]);
            q.z = __ldg(&W[(size_t)(4*j + 2) * N + n]);
            q.w = __ldg(&W[(size_t)(4*j + 3) * N + n]);
            wt[j] = q;
            o[j]  = __ldg(reinterpret_cast<const float4*>(b) + j);
        }
    }

    // ---- Phase A2: row-min partial (int4-vectorized grid-stride) ----
    int m = 0x7fffffff;
    {
        int E4 = E >> 2;
        const int4* r4 = reinterpret_cast<const int4*>(ei);
        for (int i = blockIdx.x * TPB + tid; i < E4; i += gstride) {
            int4 q = __ldg(&r4[i]);
            m = min(m, min(min(q.x, q.y), min(q.z, q.w)));
        }
        for (int k = (E4 << 2) + blockIdx.x * TPB + tid; k < E; k += gstride)
            m = min(m, __ldg(&ei[k]));
    }
    __shared__ int s_wmin[8];
    #pragma unroll
    for (int off = 16; off > 0; off >>= 1)
        m = min(m, __shfl_xor_sync(0xffffffffu, m, off));
    if ((tid & 31) == 0) s_wmin[tid >> 5] = m;
    __syncthreads();
    if (tid == 0) {
        int bm = s_wmin[0];
        #pragma unroll
        for (int k = 1; k < 8; k++) bm = min(bm, s_wmin[k]);
        g_part2[blockIdx.x] = bm;                     // plain store (every slot, every call)
    }

    // ---- Single-wave barrier (ticket counter; monotonic across graph replays) ----
    __syncthreads();
    if (tid == 0) {
        __threadfence();                              // publish Wt, out, partial
        unsigned t = atomicAdd(&g_arrive, 1u);
        unsigned target = (t / GRID + 1u) * GRID;
        while (*((volatile unsigned*)&g_arrive) < target)
            __nanosleep(128);
        __threadfence();                              // acquire side
    }
    __syncthreads();

    // ---- Phase B prologue: every CTA reduces the GRID partials locally ----
    __shared__ int s_minr;
    if (tid < 32) {
        int a = 0x7fffffff;
        for (int i = tid; i < GRID; i += 32)
            a = min(a, *((volatile int*)&g_part2[i]));
        #pragma unroll
        for (int off = 16; off > 0; off >>= 1)
            a = min(a, __shfl_xor_sync(0xffffffffu, a, off));
        if (tid == 0) s_minr = a;
    }
    __syncthreads();
    const int minr = s_minr;

    // ---- Phase B: persistent scatter (R14-proven body) ----
    int half = (E + 1) >> 1;
    long long total = (long long)half * 8;
    long long sstride = (long long)GRID * TPB;

    for (long long slot = (long long)blockIdx.x * TPB + tid; slot < total; slot += sstride) {
        long long g = slot >> 3;
        int t4 = (int)(slot & 7);

        int e0 = (int)g;
        int e1 = e0 + half;
        bool has1 = (e1 < E);

        int row0 = __ldg(&ei[e0]);
        int col0 = __ldg(&ei[E + e0]);
        int row1 = has1 ? __ldg(&ei[e1]) : 0;
        int col1 = has1 ? __ldg(&ei[E + e1]) : 0;

        row0 -= minr;  row1 -= minr;
        bool ok0 = (unsigned)row0 < (unsigned)N && (unsigned)col0 < (unsigned)N;
        bool ok1 = has1 && (unsigned)row1 < (unsigned)N && (unsigned)col1 < (unsigned)N;

        float4 v0, v1;
        if (ok0) v0 = __ldg(reinterpret_cast<const float4*>(&g_Wt[(size_t)col0 * OUT_CH]) + t4);
        if (ok1) v1 = __ldg(reinterpret_cast<const float4*>(&g_Wt[(size_t)col1 * OUT_CH]) + t4);

        if (ok0) {
            float* dst = &out[(size_t)row0 * OUT_CH + t4 * 4];
            asm volatile("red.global.add.v4.f32 [%0], {%1, %2, %3, %4};"
                         :: "l"(dst), "f"(v0.x), "f"(v0.y), "f"(v0.z), "f"(v0.w) : "memory");
        }
        if (ok1) {
            float* dst = &out[(size_t)row1 * OUT_CH + t4 * 4];
            asm volatile("red.global.add.v4.f32 [%0], {%1, %2, %3, %4};"
                         :: "l"(dst), "f"(v1.x), "f"(v1.y), "f"(v1.z), "f"(v1.w) : "memory");
        }
    }
}

// ---------------------------------------------------------------------------
extern "C" void kernel_launch(void* const* d_in, const int* in_sizes, int n_in,
                              void* d_out, int out_size) {
    const int*   ei = (const int*)d_in[0];     // [2, E]
    const float* W  = (const float*)d_in[1];   // [32, N]
    const float* b  = (const float*)d_in[2];   // [32]
    float* out = (float*)d_out;                // [N, 32]

    int E = in_sizes[0] / 2;
    int N = in_sizes[1] / OUT_CH;

    fused_kernel<<<GRID, TPB>>>(ei, W, b, out, E, N);
}

// round 17
// speedup vs baseline: 1.3419x; 1.3419x over previous
#include <cuda_runtime.h>
#include <cuda_bf16.h>
#include <stdint.h>

#define OUT_CH 32
#define MIN_BLOCKS 64

__device__ float g_Wt[100000 * OUT_CH];       // transposed W, L2-resident 12.8 MB
__device__ int   g_part[MIN_BLOCKS];          // row-min partials (rewritten every call)
__device__ int   g_rowmin;                    // finalized by last-arriving prep block
__device__ unsigned g_ticket;                 // persistent; mod-64 logic is replay-safe

// ---------------------------------------------------------------------------
// K1 (fused prep): blocks [0, NB): transpose W[32,N]->Wt[N,32] and out[n,:]=b.
//                  blocks [NB, NB+64): row-min partials (int4 loads); the
//                  last-arriving block finalizes g_rowmin (ticket; no reset).
// ---------------------------------------------------------------------------
__global__ void prep_kernel(const float* __restrict__ W, const float* __restrict__ b,
                            const int* __restrict__ rows, float* __restrict__ out,
                            int N, int E, int NB) {
    if ((int)blockIdx.x < NB) {
        int n = blockIdx.x * blockDim.x + threadIdx.x;
        if (n >= N) return;
        float v[OUT_CH];
        #pragma unroll
        for (int c = 0; c < OUT_CH; c++)
            v[c] = __ldg(&W[(size_t)c * N + n]);
        float4* dst = reinterpret_cast<float4*>(&g_Wt[(size_t)n * OUT_CH]);
        #pragma unroll
        for (int j = 0; j < OUT_CH / 4; j++)
            dst[j] = make_float4(v[4*j+0], v[4*j+1], v[4*j+2], v[4*j+3]);
        float4* o = reinterpret_cast<float4*>(&out[(size_t)n * OUT_CH]);
        #pragma unroll
        for (int j = 0; j < OUT_CH / 4; j++)
            o[j] = __ldg(reinterpret_cast<const float4*>(b) + j);
    } else {
        __shared__ int s_wmin[8];
        __shared__ int s_last;
        int blk = blockIdx.x - NB;                    // 0..63
        int m = 0x7fffffff;
        // int4-vectorized grid-stride over rows[0..E)
        int E4 = E >> 2;
        int i = blk * blockDim.x + threadIdx.x;
        int stride = MIN_BLOCKS * blockDim.x;
        const int4* r4 = reinterpret_cast<const int4*>(rows);
        for (; i < E4; i += stride) {
            int4 q = __ldg(&r4[i]);
            m = min(m, min(min(q.x, q.y), min(q.z, q.w)));
        }
        // tail
        for (int k = (E4 << 2) + blk * blockDim.x + threadIdx.x; k < E; k += stride)
            m = min(m, __ldg(&rows[k]));
        #pragma unroll
        for (int off = 16; off > 0; off >>= 1)
            m = min(m, __shfl_xor_sync(0xffffffffu, m, off));
        if ((threadIdx.x & 31) == 0) s_wmin[threadIdx.x >> 5] = m;
        __syncthreads();
        if (threadIdx.x == 0) {
            int bm = s_wmin[0];
            #pragma unroll
            for (int k = 1; k < 8; k++) bm = min(bm, s_wmin[k]);
            g_part[blk] = bm;                         // plain store
            __threadfence();
            unsigned t = atomicAdd(&g_ticket, 1u);    // persistent; mod-64 replay-safe
            s_last = ((t & 63u) == 63u) ? 1 : 0;
        }
        __syncthreads();
        if (s_last && threadIdx.x < 32) {
            volatile int* vp = g_part;
            int a = min(vp[threadIdx.x], vp[threadIdx.x + 32]);
            #pragma unroll
            for (int off = 16; off > 0; off >>= 1)
                a = min(a, __shfl_xor_sync(0xffffffffu, a, off));
            if (threadIdx.x == 0) g_rowmin = a;
        }
    }
}

// ---------------------------------------------------------------------------
// K2: persistent scatter. Single wave of CTAs; grid-stride over edge-pair
// slots (8 threads per slot, 2 independent edges per thread). Loop iterations
// are independent -> HW overlaps next iteration's loads with this one's REDs.
// ---------------------------------------------------------------------------
__global__ void __launch_bounds__(256) scatter_kernel(const int* __restrict__ ei,
                                                      int E, int N,
                                                      float* __restrict__ out) {
    int minr = g_rowmin;                              // single uniform load
    int half = (E + 1) >> 1;
    long long total = (long long)half * 8;
    long long stride = (long long)gridDim.x * blockDim.x;

    for (long long slot = (long long)blockIdx.x * blockDim.x + threadIdx.x;
         slot < total; slot += stride) {
        long long g = slot >> 3;
        int t = (int)(slot & 7);

        int e0 = (int)g;
        int e1 = e0 + half;
        bool has1 = (e1 < E);

        int row0 = __ldg(&ei[e0]);
        int col0 = __ldg(&ei[E + e0]);
        int row1 = has1 ? __ldg(&ei[e1]) : 0;
        int col1 = has1 ? __ldg(&ei[E + e1]) : 0;

        row0 -= minr;  row1 -= minr;
        bool ok0 = (unsigned)row0 < (unsigned)N && (unsigned)col0 < (unsigned)N;
        bool ok1 = has1 && (unsigned)row1 < (unsigned)N && (unsigned)col1 < (unsigned)N;

        float4 v0, v1;
        if (ok0) v0 = __ldg(reinterpret_cast<const float4*>(&g_Wt[(size_t)col0 * OUT_CH]) + t);
        if (ok1) v1 = __ldg(reinterpret_cast<const float4*>(&g_Wt[(size_t)col1 * OUT_CH]) + t);

        if (ok0) {
            float* dst = &out[(size_t)row0 * OUT_CH + t * 4];
            asm volatile("red.global.add.v4.f32 [%0], {%1, %2, %3, %4};"
                         :: "l"(dst), "f"(v0.x), "f"(v0.y), "f"(v0.z), "f"(v0.w) : "memory");
        }
        if (ok1) {
            float* dst = &out[(size_t)row1 * OUT_CH + t * 4];
            asm volatile("red.global.add.v4.f32 [%0], {%1, %2, %3, %4};"
                         :: "l"(dst), "f"(v1.x), "f"(v1.y), "f"(v1.z), "f"(v1.w) : "memory");
        }
    }
}

// ---------------------------------------------------------------------------
extern "C" void kernel_launch(void* const* d_in, const int* in_sizes, int n_in,
                              void* d_out, int out_size) {
    const int*   ei = (const int*)d_in[0];     // [2, E]
    const float* W  = (const float*)d_in[1];   // [32, N]
    const float* b  = (const float*)d_in[2];   // [32]
    float* out = (float*)d_out;                // [N, 32]

    int E = in_sizes[0] / 2;
    int N = in_sizes[1] / OUT_CH;

    int pthreads = 256;
    int NB = (N + pthreads - 1) / pthreads;
    prep_kernel<<<NB + MIN_BLOCKS, pthreads>>>(W, b, ei, out, N, E, NB);

    // persistent single wave: 148 SMs x 8 CTAs of 256 threads
    int sthreads = 256;
    int sblocks = 148 * 8;
    scatter_kernel<<<sblocks, sthreads>>>(ei, E, N, out);
}